// round 4
// baseline (speedup 1.0000x reference)
#include <cuda_runtime.h>
#include <math.h>

#define NHN 50000
#define NON 50000
#define NEN 500000
#define DN  256
#define LN  8
#define BNB 512
#define CNC 117

// ---------------- device scratch (static: allocation-free rule) ----------------
__device__ __align__(16) float g_xh[2][NHN*DN];
__device__ __align__(16) float g_xo[2][NON*DN];
__device__ __align__(16) float g_agg_h[NHN*DN];
__device__ __align__(16) float g_agg_o[NON*DN];
__device__ float g_logit_ho[NEN];
__device__ float g_ex_ho[NEN];
__device__ float g_logit_oh[NEN];
__device__ float g_ex_oh[NEN];
__device__ float g_as_ho[NHN];
__device__ float g_ad_ho[NON];
__device__ float g_as_oh[NON];
__device__ float g_ad_oh[NHN];
__device__ unsigned g_menc_ho[NON];
__device__ float    g_den_ho[NON];
__device__ unsigned g_menc_oh[NHN];
__device__ float    g_den_oh[NHN];
__device__ __align__(16) float g_wvec[4][DN];   // 0:wsa_ho 1:wda_ho 2:wsa_oh 3:wda_oh
__device__ float g_cvec[4];                      // c_ho[2], c_oh[2]
__device__ __align__(16) float g_hpool[BNB*DN];
__device__ __align__(16) float g_opool[BNB*DN];
__device__ float g_epool[BNB*32];
__device__ int g_starts_h[BNB+1];
__device__ int g_starts_o[BNB+1];
__device__ int g_cnt_e[BNB];

// ---------------- helpers ----------------
__device__ __forceinline__ unsigned f2ord(float f) {
    unsigned u = __float_as_uint(f);
    return (u & 0x80000000u) ? ~u : (u | 0x80000000u);
}
__device__ __forceinline__ float ord2f(unsigned v) {
    unsigned u = (v & 0x80000000u) ? (v & 0x7fffffffu) : ~v;
    return __uint_as_float(u);
}
__device__ __forceinline__ void red_add4(float* p, float4 v) {
    asm volatile("red.global.add.v4.f32 [%0], {%1,%2,%3,%4};"
                 :: "l"(p), "f"(v.x), "f"(v.y), "f"(v.z), "f"(v.w) : "memory");
}

// ---------------- per-layer small weights: wvec[k] = W[l] @ avec, cvec = Wedge[l] @ aedge[l]
__global__ void k_small(const float* WsrcHo, const float* asrcHo,
                        const float* WdstHo, const float* adstHo,
                        const float* WsrcOh, const float* asrcOh,
                        const float* WdstOh, const float* adstOh,
                        const float* WedgeHo, const float* aedgeHo,
                        const float* WedgeOh, const float* aedgeOh, int l)
{
    int k = threadIdx.x;
    const float* W0 = WsrcHo + (size_t)l*DN*DN + (size_t)k*DN;
    const float* W1 = WdstHo + (size_t)l*DN*DN + (size_t)k*DN;
    const float* W2 = WsrcOh + (size_t)l*DN*DN + (size_t)k*DN;
    const float* W3 = WdstOh + (size_t)l*DN*DN + (size_t)k*DN;
    const float* a0 = asrcHo + l*DN;
    const float* a1 = adstHo + l*DN;
    const float* a2 = asrcOh + l*DN;
    const float* a3 = adstOh + l*DN;
    float s0 = 0.f, s1 = 0.f, s2 = 0.f, s3 = 0.f;
    for (int n = 0; n < DN; n++) {
        s0 += W0[n] * a0[n];
        s1 += W1[n] * a1[n];
        s2 += W2[n] * a2[n];
        s3 += W3[n] * a3[n];
    }
    g_wvec[0][k] = s0; g_wvec[1][k] = s1; g_wvec[2][k] = s2; g_wvec[3][k] = s3;
    if (k < 2) {
        float c = 0.f;
        const float* We = WedgeHo + (size_t)l*2*DN + (size_t)k*DN;
        const float* ae = aedgeHo + l*DN;
        for (int n = 0; n < DN; n++) c += We[n] * ae[n];
        g_cvec[k] = c;
    } else if (k < 4) {
        int r = k - 2;
        float c = 0.f;
        const float* We = WedgeOh + (size_t)l*2*DN + (size_t)r*DN;
        const float* ae = aedgeOh + l*DN;
        for (int n = 0; n < DN; n++) c += We[n] * ae[n];
        g_cvec[k] = c;
    }
}

// ---------------- node scores: two dot products per node (warp per node)
__global__ void k_nodescore(const float* __restrict__ x, int ia, int ib,
                            float* __restrict__ outA, float* __restrict__ outB, int N)
{
    int w = (blockIdx.x * blockDim.x + threadIdx.x) >> 5;
    int lane = threadIdx.x & 31;
    if (w >= N) return;
    const float4* xr = (const float4*)(x + (size_t)w * DN);
    const float4* va = (const float4*)g_wvec[ia];
    const float4* vb = (const float4*)g_wvec[ib];
    float4 x0 = xr[lane], x1 = xr[lane + 32];
    float4 a0 = va[lane], a1 = va[lane + 32];
    float4 b0 = vb[lane], b1 = vb[lane + 32];
    float dA = x0.x*a0.x + x0.y*a0.y + x0.z*a0.z + x0.w*a0.w
             + x1.x*a1.x + x1.y*a1.y + x1.z*a1.z + x1.w*a1.w;
    float dB = x0.x*b0.x + x0.y*b0.y + x0.z*b0.z + x0.w*b0.w
             + x1.x*b1.x + x1.y*b1.y + x1.z*b1.z + x1.w*b1.w;
    #pragma unroll
    for (int off = 16; off > 0; off >>= 1) {
        dA += __shfl_down_sync(0xffffffffu, dA, off);
        dB += __shfl_down_sync(0xffffffffu, dB, off);
    }
    if (lane == 0) { outA[w] = dA; outB[w] = dB; }
}

// ---------------- edge pass A: logit + segment max
__global__ void k_edgeA(const int* __restrict__ src, const int* __restrict__ dst,
                        const float* __restrict__ ea,
                        const float* __restrict__ a_s, const float* __restrict__ a_d,
                        const float* __restrict__ cpair,
                        float* __restrict__ logit, unsigned* __restrict__ menc)
{
    int e = blockIdx.x * blockDim.x + threadIdx.x;
    if (e >= NEN) return;
    int s = src[e], d = dst[e];
    float2 at = ((const float2*)ea)[e];
    float lg = a_s[s] + a_d[d] + at.x * cpair[0] + at.y * cpair[1];
    lg = (lg > 0.f) ? lg : 0.2f * lg;
    logit[e] = lg;
    atomicMax(&menc[d], f2ord(lg));
}

// ---------------- edge pass B: exp + segment sum
__global__ void k_edgeB(const int* __restrict__ dst,
                        const float* __restrict__ logit, const unsigned* __restrict__ menc,
                        float* __restrict__ ex, float* __restrict__ den)
{
    int e = blockIdx.x * blockDim.x + threadIdx.x;
    if (e >= NEN) return;
    int d = dst[e];
    float v = __expf(logit[e] - ord2f(menc[d]));
    ex[e] = v;
    atomicAdd(&den[d], v);
}

// ---------------- edge pass C: weighted gather + scatter-add (warp per edge)
__global__ void k_edgeC(const int* __restrict__ src, const int* __restrict__ dst,
                        const float* __restrict__ ex, const float* __restrict__ den,
                        const float* __restrict__ x, float* __restrict__ agg)
{
    int e = (blockIdx.x * blockDim.x + threadIdx.x) >> 5;
    if (e >= NEN) return;
    int lane = threadIdx.x & 31;
    int s = src[e], d = dst[e];
    float w = ex[e] / den[d];
    const float4* xs = (const float4*)(x + (size_t)s * DN);
    float4 v0 = xs[lane], v1 = xs[lane + 32];
    v0.x *= w; v0.y *= w; v0.z *= w; v0.w *= w;
    v1.x *= w; v1.y *= w; v1.z *= w; v1.w *= w;
    float* base = agg + (size_t)d * DN;
    red_add4(base + lane * 4, v0);
    red_add4(base + 128 + lane * 4, v1);
}

// ---------------- GEMM: out = relu(A @ W + bias) [+ resid]; 128x128 tile, 256 thr
__global__ void k_gemm(const float* __restrict__ A, const float* __restrict__ W,
                       const float* __restrict__ bias, const float* __restrict__ resid,
                       float* __restrict__ Cmat, int M)
{
    __shared__ float As[16][128];
    __shared__ float Bs[16][128];
    int tid = threadIdx.x;
    int rowBase = blockIdx.y * 128, colBase = blockIdx.x * 128;
    int tx = tid & 15, ty = tid >> 4;
    float acc[8][8];
    #pragma unroll
    for (int i = 0; i < 8; i++)
        #pragma unroll
        for (int j = 0; j < 8; j++) acc[i][j] = 0.f;

    int ar = tid >> 2, ac4 = tid & 3;     // A: rows ar, ar+64; k-quad ac4
    int bk = tid >> 5, bn4 = tid & 31;    // B: k rows bk, bk+8; col-quad bn4

    for (int k0 = 0; k0 < DN; k0 += 16) {
        int r0 = rowBase + ar, r1 = rowBase + ar + 64;
        float4 av0 = make_float4(0.f,0.f,0.f,0.f), av1 = av0;
        if (r0 < M) av0 = *(const float4*)&A[(size_t)r0 * DN + k0 + ac4 * 4];
        if (r1 < M) av1 = *(const float4*)&A[(size_t)r1 * DN + k0 + ac4 * 4];
        As[ac4*4+0][ar] = av0.x; As[ac4*4+1][ar] = av0.y;
        As[ac4*4+2][ar] = av0.z; As[ac4*4+3][ar] = av0.w;
        As[ac4*4+0][ar+64] = av1.x; As[ac4*4+1][ar+64] = av1.y;
        As[ac4*4+2][ar+64] = av1.z; As[ac4*4+3][ar+64] = av1.w;
        *(float4*)&Bs[bk][bn4*4]   = *(const float4*)&W[(size_t)(k0+bk)*DN + colBase + bn4*4];
        *(float4*)&Bs[bk+8][bn4*4] = *(const float4*)&W[(size_t)(k0+bk+8)*DN + colBase + bn4*4];
        __syncthreads();
        #pragma unroll
        for (int k = 0; k < 16; k++) {
            float4 a0 = *(const float4*)&As[k][ty*8];
            float4 a1 = *(const float4*)&As[k][ty*8+4];
            float4 b0 = *(const float4*)&Bs[k][tx*8];
            float4 b1 = *(const float4*)&Bs[k][tx*8+4];
            float ra[8] = {a0.x,a0.y,a0.z,a0.w,a1.x,a1.y,a1.z,a1.w};
            float rb[8] = {b0.x,b0.y,b0.z,b0.w,b1.x,b1.y,b1.z,b1.w};
            #pragma unroll
            for (int i = 0; i < 8; i++)
                #pragma unroll
                for (int j = 0; j < 8; j++) acc[i][j] += ra[i] * rb[j];
        }
        __syncthreads();
    }
    #pragma unroll
    for (int i = 0; i < 8; i++) {
        int r = rowBase + ty*8 + i;
        if (r >= M) continue;
        #pragma unroll
        for (int jj = 0; jj < 2; jj++) {
            int c = colBase + tx*8 + jj*4;
            float4 bv = *(const float4*)&bias[c];
            float4 v;
            v.x = fmaxf(acc[i][jj*4+0] + bv.x, 0.f);
            v.y = fmaxf(acc[i][jj*4+1] + bv.y, 0.f);
            v.z = fmaxf(acc[i][jj*4+2] + bv.z, 0.f);
            v.w = fmaxf(acc[i][jj*4+3] + bv.w, 0.f);
            if (resid) {
                float4 rv = *(const float4*)&resid[(size_t)r * DN + c];
                v.x += rv.x; v.y += rv.y; v.z += rv.z; v.w += rv.w;
            }
            *(float4*)&Cmat[(size_t)r * DN + c] = v;
        }
    }
}

// ---------------- batch segment boundaries from sorted batch vector
__global__ void k_starts(const int* __restrict__ batch, int* __restrict__ starts, int N)
{
    int i = blockIdx.x * blockDim.x + threadIdx.x;
    if (i >= N) return;
    int b = batch[i];
    int prev = (i == 0) ? -1 : batch[i - 1];
    for (int v = prev + 1; v <= b; v++) starts[v] = i;
    if (i == N - 1)
        for (int v = b + 1; v <= BNB; v++) starts[v] = N;
}

// ---------------- segment-mean pooling (block per batch, thread per column)
__global__ void k_pool(const float* __restrict__ x, const int* __restrict__ starts,
                       float* __restrict__ pool)
{
    int b = blockIdx.x, c = threadIdx.x;
    int s0 = starts[b], s1 = starts[b + 1];
    float acc = 0.f;
    for (int i = s0; i < s1; i++) acc += x[(size_t)i * DN + c];
    pool[b * DN + c] = acc / fmaxf((float)(s1 - s0), 1.f);
}

// ---------------- edge MLP pooling (warp per edge, lane per output channel)
__global__ void k_epool(const int* __restrict__ src, const float* __restrict__ ea,
                        const int* __restrict__ hbatch,
                        const float* __restrict__ Wem, const float* __restrict__ bem)
{
    __shared__ int hist[BNB];
    for (int t = threadIdx.x; t < BNB; t += blockDim.x) hist[t] = 0;
    __syncthreads();
    int lane = threadIdx.x & 31;
    int wid = (blockIdx.x * blockDim.x + threadIdx.x) >> 5;
    int nw = (gridDim.x * blockDim.x) >> 5;
    float w0 = Wem[lane], w1 = Wem[32 + lane], bb = bem[lane];
    for (int e = wid; e < NEN; e += nw) {
        int b = hbatch[src[e]];
        float2 at = ((const float2*)ea)[e];
        float v = fmaxf(at.x * w0 + at.y * w1 + bb, 0.f);
        atomicAdd(&g_epool[b * 32 + lane], v);
        if (lane == 0) atomicAdd(&hist[b], 1);
    }
    __syncthreads();
    for (int t = threadIdx.x; t < BNB; t += blockDim.x)
        if (hist[t]) atomicAdd(&g_cnt_e[t], hist[t]);
}

__global__ void k_epool_div()
{
    int i = blockIdx.x * blockDim.x + threadIdx.x;
    if (i >= BNB * 32) return;
    g_epool[i] /= fmaxf((float)g_cnt_e[i >> 5], 1.f);
}

// ---------------- final heads: linear + softmax (block per (batch, head))
__global__ void k_head(const float* __restrict__ Wp1, const float* __restrict__ bp1,
                       const float* __restrict__ Wp2, const float* __restrict__ bp2,
                       float* __restrict__ out)
{
    __shared__ float emb[2*DN + 32];
    __shared__ float red[128];
    int b = blockIdx.x, head = blockIdx.y, t = threadIdx.x;
    for (int i = t; i < DN; i += 128) {
        emb[i] = g_hpool[b * DN + i];
        emb[DN + i] = g_opool[b * DN + i];
    }
    if (t < 32) emb[2*DN + t] = g_epool[b * 32 + t];
    __syncthreads();
    const float* Wp = head ? Wp2 : Wp1;
    const float* bp = head ? bp2 : bp1;
    float acc = -INFINITY;
    if (t < CNC) {
        acc = bp[t];
        for (int k = 0; k < 2*DN + 32; k++) acc += emb[k] * Wp[k * CNC + t];
    }
    // block max
    red[t] = acc;
    __syncthreads();
    for (int s = 64; s > 0; s >>= 1) {
        if (t < s) red[t] = fmaxf(red[t], red[t + s]);
        __syncthreads();
    }
    float mx = red[0];
    __syncthreads();
    float ex = (t < CNC) ? __expf(acc - mx) : 0.f;
    red[t] = ex;
    __syncthreads();
    for (int s = 64; s > 0; s >>= 1) {
        if (t < s) red[t] += red[t + s];
        __syncthreads();
    }
    float sum = red[0];
    if (t < CNC) out[((size_t)b * 2 + head) * CNC + t] = ex / sum;
}

// ---------------- host ----------------
#define SYM(p, s) do { void* tmp__ = 0; cudaGetSymbolAddress(&tmp__, s); p = (decltype(p))tmp__; } while (0)

extern "C" void kernel_launch(void* const* d_in, const int* in_sizes, int n_in,
                              void* d_out, int out_size)
{
    const float* x_human  = (const float*)d_in[0];
    const float* x_object = (const float*)d_in[1];
    const int*   ei_ho    = (const int*)d_in[2];
    const int*   ei_oh    = (const int*)d_in[3];
    const float* ea_ho    = (const float*)d_in[4];
    const float* ea_oh    = (const float*)d_in[5];
    const int*   hbatch   = (const int*)d_in[6];
    const int*   obatch   = (const int*)d_in[7];
    const float* Wsrc_ho  = (const float*)d_in[8];
    const float* Wdst_ho  = (const float*)d_in[9];
    const float* asrc_ho  = (const float*)d_in[10];
    const float* adst_ho  = (const float*)d_in[11];
    const float* Wedge_ho = (const float*)d_in[12];
    const float* aedge_ho = (const float*)d_in[13];
    const float* bias_ho  = (const float*)d_in[14];
    const float* Wsrc_oh  = (const float*)d_in[15];
    const float* Wdst_oh  = (const float*)d_in[16];
    const float* asrc_oh  = (const float*)d_in[17];
    const float* adst_oh  = (const float*)d_in[18];
    const float* Wedge_oh = (const float*)d_in[19];
    const float* aedge_oh = (const float*)d_in[20];
    const float* bias_oh  = (const float*)d_in[21];
    const float* W_emlp   = (const float*)d_in[22];
    const float* b_emlp   = (const float*)d_in[23];
    const float* W_p1     = (const float*)d_in[24];
    const float* b_p1     = (const float*)d_in[25];
    const float* W_p2     = (const float*)d_in[26];
    const float* b_p2     = (const float*)d_in[27];

    float *xh0, *xo0, *agg_h, *agg_o;
    float *logit_ho, *ex_ho, *logit_oh, *ex_oh;
    float *as_ho, *ad_ho, *as_oh, *ad_oh;
    unsigned *menc_ho, *menc_oh;
    float *den_ho, *den_oh, *cvec;
    float *hpool, *opool, *epool;
    int *starts_h, *starts_o, *cnt_e;
    SYM(xh0, g_xh);        SYM(xo0, g_xo);
    SYM(agg_h, g_agg_h);   SYM(agg_o, g_agg_o);
    SYM(logit_ho, g_logit_ho); SYM(ex_ho, g_ex_ho);
    SYM(logit_oh, g_logit_oh); SYM(ex_oh, g_ex_oh);
    SYM(as_ho, g_as_ho); SYM(ad_ho, g_ad_ho);
    SYM(as_oh, g_as_oh); SYM(ad_oh, g_ad_oh);
    SYM(menc_ho, g_menc_ho); SYM(den_ho, g_den_ho);
    SYM(menc_oh, g_menc_oh); SYM(den_oh, g_den_oh);
    SYM(cvec, g_cvec);
    SYM(hpool, g_hpool); SYM(opool, g_opool); SYM(epool, g_epool);
    SYM(starts_h, g_starts_h); SYM(starts_o, g_starts_o); SYM(cnt_e, g_cnt_e);
    float* xh1 = xh0 + (size_t)NHN * DN;
    float* xo1 = xo0 + (size_t)NON * DN;

    cudaMemcpyAsync(xh0, x_human,  sizeof(float)*(size_t)NHN*DN, cudaMemcpyDeviceToDevice, 0);
    cudaMemcpyAsync(xo0, x_object, sizeof(float)*(size_t)NON*DN, cudaMemcpyDeviceToDevice, 0);

    int nsBlocksH = (NHN * 32 + 255) / 256;
    int nsBlocksO = (NON * 32 + 255) / 256;
    int eBlocks   = (NEN + 255) / 256;
    int cBlocks   = (NEN * 32) / 256;
    dim3 gg(2, (NON + 127) / 128);

    int cur = 0;
    for (int l = 0; l < LN; l++) {
        float* xh_in  = cur ? xh1 : xh0;
        float* xh_out = cur ? xh0 : xh1;
        float* xo_in  = cur ? xo1 : xo0;
        float* xo_out = cur ? xo0 : xo1;

        k_small<<<1, 256>>>(Wsrc_ho, asrc_ho, Wdst_ho, adst_ho,
                            Wsrc_oh, asrc_oh, Wdst_oh, adst_oh,
                            Wedge_ho, aedge_ho, Wedge_oh, aedge_oh, l);
        cudaMemsetAsync(agg_h, 0, sizeof(float)*(size_t)NHN*DN, 0);
        cudaMemsetAsync(agg_o, 0, sizeof(float)*(size_t)NON*DN, 0);
        cudaMemsetAsync(menc_ho, 0, sizeof(unsigned)*NON, 0);
        cudaMemsetAsync(den_ho,  0, sizeof(float)*NON, 0);
        cudaMemsetAsync(menc_oh, 0, sizeof(unsigned)*NHN, 0);
        cudaMemsetAsync(den_oh,  0, sizeof(float)*NHN, 0);

        k_nodescore<<<nsBlocksH, 256>>>(xh_in, 0, 3, as_ho, ad_oh, NHN);
        k_nodescore<<<nsBlocksO, 256>>>(xo_in, 2, 1, as_oh, ad_ho, NON);

        k_edgeA<<<eBlocks, 256>>>(ei_ho, ei_ho + NEN, ea_ho, as_ho, ad_ho, cvec,     logit_ho, menc_ho);
        k_edgeA<<<eBlocks, 256>>>(ei_oh, ei_oh + NEN, ea_oh, as_oh, ad_oh, cvec + 2, logit_oh, menc_oh);
        k_edgeB<<<eBlocks, 256>>>(ei_ho + NEN, logit_ho, menc_ho, ex_ho, den_ho);
        k_edgeB<<<eBlocks, 256>>>(ei_oh + NEN, logit_oh, menc_oh, ex_oh, den_oh);
        k_edgeC<<<cBlocks, 256>>>(ei_ho, ei_ho + NEN, ex_ho, den_ho, xh_in, agg_o);
        k_edgeC<<<cBlocks, 256>>>(ei_oh, ei_oh + NEN, ex_oh, den_oh, xo_in, agg_h);

        k_gemm<<<gg, 256>>>(agg_o, Wsrc_ho + (size_t)l*DN*DN, bias_ho + l*DN,
                            l ? xo_in : (const float*)0, xo_out, NON);
        k_gemm<<<gg, 256>>>(agg_h, Wsrc_oh + (size_t)l*DN*DN, bias_oh + l*DN,
                            l ? xh_in : (const float*)0, xh_out, NHN);
        cur ^= 1;
    }
    float* xh_fin = cur ? xh1 : xh0;
    float* xo_fin = cur ? xo1 : xo0;

    k_starts<<<(NHN + 255) / 256, 256>>>(hbatch, starts_h, NHN);
    k_starts<<<(NON + 255) / 256, 256>>>(obatch, starts_o, NON);
    k_pool<<<BNB, 256>>>(xh_fin, starts_h, hpool);
    k_pool<<<BNB, 256>>>(xo_fin, starts_o, opool);

    cudaMemsetAsync(epool, 0, sizeof(float)*BNB*32, 0);
    cudaMemsetAsync(cnt_e, 0, sizeof(int)*BNB, 0);
    k_epool<<<512, 256>>>(ei_ho, ea_ho, hbatch, W_emlp, b_emlp);
    k_epool_div<<<(BNB*32 + 255) / 256, 256>>>();

    k_head<<<dim3(BNB, 2), 128>>>(W_p1, b_p1, W_p2, b_p2, (float*)d_out);
}

// round 5
// speedup vs baseline: 1.1740x; 1.1740x over previous
#include <cuda_runtime.h>
#include <math.h>

#define NHN 50000
#define NON 50000
#define NEN 500000
#define DN  256
#define LN  8
#define BNB 512
#define CNC 117

// ---------------- device scratch (static: allocation-free rule) ----------------
__device__ __align__(16) float g_xh[2][NHN*DN];
__device__ __align__(16) float g_xo[2][NON*DN];
__device__ __align__(16) float g_agg_h[NHN*DN];
__device__ __align__(16) float g_agg_o[NON*DN];
__device__ float g_ex_ho[NEN];
__device__ float g_ex_oh[NEN];
__device__ float g_as_ho[NHN];
__device__ float g_ad_ho[NON];
__device__ float g_as_oh[NON];
__device__ float g_ad_oh[NHN];
__device__ float g_den_ho[NON];
__device__ float g_den_oh[NHN];
__device__ __align__(16) float g_wvec[4][DN];   // 0:wsa_ho 1:wda_ho 2:wsa_oh 3:wda_oh
__device__ float g_cvec[4];                      // c_ho[2], c_oh[2]
__device__ __align__(16) float g_hpool[BNB*DN];
__device__ __align__(16) float g_opool[BNB*DN];
__device__ float g_epool[BNB*32];
__device__ int g_starts_h[BNB+1];
__device__ int g_starts_o[BNB+1];
__device__ int g_cnt_e[BNB];

// ---------------- helpers ----------------
__device__ __forceinline__ void red_add4(float* p, float4 v) {
    asm volatile("red.global.add.v4.f32 [%0], {%1,%2,%3,%4};"
                 :: "l"(p), "f"(v.x), "f"(v.y), "f"(v.z), "f"(v.w) : "memory");
}
__device__ __forceinline__ unsigned f2tf(float v) {
    unsigned r;
    asm("cvt.rna.tf32.f32 %0, %1;" : "=r"(r) : "f"(v));
    return r;
}
__device__ __forceinline__ void mma_tf32(float* d, const unsigned* a, const unsigned* b) {
    asm volatile("mma.sync.aligned.m16n8k8.row.col.f32.tf32.tf32.f32 "
                 "{%0,%1,%2,%3}, {%4,%5,%6,%7}, {%8,%9}, {%0,%1,%2,%3};"
                 : "+f"(d[0]), "+f"(d[1]), "+f"(d[2]), "+f"(d[3])
                 : "r"(a[0]), "r"(a[1]), "r"(a[2]), "r"(a[3]),
                   "r"(b[0]), "r"(b[1]));
}

// ---------------- per-layer small weights: wvec[k] = W[l] @ avec, cvec = Wedge[l] @ aedge[l]
__global__ void k_small(const float* WsrcHo, const float* asrcHo,
                        const float* WdstHo, const float* adstHo,
                        const float* WsrcOh, const float* asrcOh,
                        const float* WdstOh, const float* adstOh,
                        const float* WedgeHo, const float* aedgeHo,
                        const float* WedgeOh, const float* aedgeOh, int l)
{
    int k = threadIdx.x;
    const float* W0 = WsrcHo + (size_t)l*DN*DN + (size_t)k*DN;
    const float* W1 = WdstHo + (size_t)l*DN*DN + (size_t)k*DN;
    const float* W2 = WsrcOh + (size_t)l*DN*DN + (size_t)k*DN;
    const float* W3 = WdstOh + (size_t)l*DN*DN + (size_t)k*DN;
    const float* a0 = asrcHo + l*DN;
    const float* a1 = adstHo + l*DN;
    const float* a2 = asrcOh + l*DN;
    const float* a3 = adstOh + l*DN;
    float s0 = 0.f, s1 = 0.f, s2 = 0.f, s3 = 0.f;
    for (int n = 0; n < DN; n++) {
        s0 += W0[n] * a0[n];
        s1 += W1[n] * a1[n];
        s2 += W2[n] * a2[n];
        s3 += W3[n] * a3[n];
    }
    g_wvec[0][k] = s0; g_wvec[1][k] = s1; g_wvec[2][k] = s2; g_wvec[3][k] = s3;
    if (k < 2) {
        float c = 0.f;
        const float* We = WedgeHo + (size_t)l*2*DN + (size_t)k*DN;
        const float* ae = aedgeHo + l*DN;
        for (int n = 0; n < DN; n++) c += We[n] * ae[n];
        g_cvec[k] = c;
    } else if (k < 4) {
        int r = k - 2;
        float c = 0.f;
        const float* We = WedgeOh + (size_t)l*2*DN + (size_t)r*DN;
        const float* ae = aedgeOh + l*DN;
        for (int n = 0; n < DN; n++) c += We[n] * ae[n];
        g_cvec[k] = c;
    }
}

// ---------------- node scores: two dot products per node (warp per node)
__global__ void k_nodescore(const float* __restrict__ x, int ia, int ib,
                            float* __restrict__ outA, float* __restrict__ outB, int N)
{
    int w = (blockIdx.x * blockDim.x + threadIdx.x) >> 5;
    int lane = threadIdx.x & 31;
    if (w >= N) return;
    const float4* xr = (const float4*)(x + (size_t)w * DN);
    const float4* va = (const float4*)g_wvec[ia];
    const float4* vb = (const float4*)g_wvec[ib];
    float4 x0 = xr[lane], x1 = xr[lane + 32];
    float4 a0 = va[lane], a1 = va[lane + 32];
    float4 b0 = vb[lane], b1 = vb[lane + 32];
    float dA = x0.x*a0.x + x0.y*a0.y + x0.z*a0.z + x0.w*a0.w
             + x1.x*a1.x + x1.y*a1.y + x1.z*a1.z + x1.w*a1.w;
    float dB = x0.x*b0.x + x0.y*b0.y + x0.z*b0.z + x0.w*b0.w
             + x1.x*b1.x + x1.y*b1.y + x1.z*b1.z + x1.w*b1.w;
    #pragma unroll
    for (int off = 16; off > 0; off >>= 1) {
        dA += __shfl_down_sync(0xffffffffu, dA, off);
        dB += __shfl_down_sync(0xffffffffu, dB, off);
    }
    if (lane == 0) { outA[w] = dA; outB[w] = dB; }
}

// ---------------- fused edge pass: logit -> exp (no max; softmax shift-invariant) + segment sum
__global__ void k_edgeAB(const int* __restrict__ src, const int* __restrict__ dst,
                         const float* __restrict__ ea,
                         const float* __restrict__ a_s, const float* __restrict__ a_d,
                         const float* __restrict__ cpair,
                         float* __restrict__ ex, float* __restrict__ den)
{
    int e = blockIdx.x * blockDim.x + threadIdx.x;
    if (e >= NEN) return;
    int s = src[e], d = dst[e];
    float2 at = ((const float2*)ea)[e];
    float lg = a_s[s] + a_d[d] + at.x * cpair[0] + at.y * cpair[1];
    lg = (lg > 0.f) ? lg : 0.2f * lg;
    float v = __expf(lg);
    ex[e] = v;
    atomicAdd(&den[d], v);
}

// ---------------- edge pass C: weighted gather + scatter-add (warp per edge)
__global__ void k_edgeC(const int* __restrict__ src, const int* __restrict__ dst,
                        const float* __restrict__ ex, const float* __restrict__ den,
                        const float* __restrict__ x, float* __restrict__ agg)
{
    int e = (blockIdx.x * blockDim.x + threadIdx.x) >> 5;
    if (e >= NEN) return;
    int lane = threadIdx.x & 31;
    int s = src[e], d = dst[e];
    float w = ex[e] / den[d];
    const float4* xs = (const float4*)(x + (size_t)s * DN);
    float4 v0 = xs[lane], v1 = xs[lane + 32];
    v0.x *= w; v0.y *= w; v0.z *= w; v0.w *= w;
    v1.x *= w; v1.y *= w; v1.z *= w; v1.w *= w;
    float* base = agg + (size_t)d * DN;
    red_add4(base + lane * 4, v0);
    red_add4(base + 128 + lane * 4, v1);
}

// ---------------- tensor-core GEMM (3xTF32): out = relu(A@W + bias) [+ resid]
// 128x128 tile, BK=16, 256 threads = 8 warps (2x4), warp tile 64x32 (4 mtiles x 4 ntiles)
#define GBK 16
__global__ void __launch_bounds__(256, 2)
k_gemm_tc(const float* __restrict__ A, const float* __restrict__ W,
          const float* __restrict__ bias, const float* __restrict__ resid,
          float* __restrict__ Cmat, int M)
{
    // A: stride 20 -> fragment bank = (4*row + k) % 32 == lane (conflict-free)
    __shared__ unsigned Ah[128][20];
    __shared__ unsigned Al[128][20];
    __shared__ unsigned Bh[GBK][132];
    __shared__ unsigned Bl[GBK][132];

    int tid  = threadIdx.x;
    int lane = tid & 31;
    int warp = tid >> 5;
    int wRow = warp >> 2;          // 0..1
    int wCol = warp & 3;           // 0..3
    int rowBase = blockIdx.y * 128;
    int colBase = blockIdx.x * 128;

    float acc[4][4][4];
    #pragma unroll
    for (int i = 0; i < 4; i++)
        #pragma unroll
        for (int j = 0; j < 4; j++)
            #pragma unroll
            for (int k = 0; k < 4; k++) acc[i][j][k] = 0.f;

    int ar = tid >> 1;             // A stage: row 0..127
    int aq = tid & 1;              // quad 0/1 (then +2)
    int bk = tid >> 5;             // B stage: k row 0..7 (then +8)
    int bq = tid & 31;             // n-quad 0..31

    for (int k0 = 0; k0 < DN; k0 += GBK) {
        // ---- stage A (128 x 16), split hi/lo
        int gr = rowBase + ar;
        #pragma unroll
        for (int qi = 0; qi < 2; qi++) {
            int qq = aq + qi * 2;
            float4 v = make_float4(0.f, 0.f, 0.f, 0.f);
            if (gr < M) v = *(const float4*)&A[(size_t)gr * DN + k0 + qq * 4];
            uint4 hi, lo;
            hi.x = f2tf(v.x); lo.x = f2tf(v.x - __uint_as_float(hi.x));
            hi.y = f2tf(v.y); lo.y = f2tf(v.y - __uint_as_float(hi.y));
            hi.z = f2tf(v.z); lo.z = f2tf(v.z - __uint_as_float(hi.z));
            hi.w = f2tf(v.w); lo.w = f2tf(v.w - __uint_as_float(hi.w));
            *(uint4*)&Ah[ar][qq * 4] = hi;
            *(uint4*)&Al[ar][qq * 4] = lo;
        }
        // ---- stage B (16 x 128), split hi/lo
        #pragma unroll
        for (int ki = 0; ki < 2; ki++) {
            int kk = bk + ki * 8;
            float4 v = *(const float4*)&W[(size_t)(k0 + kk) * DN + colBase + bq * 4];
            uint4 hi, lo;
            hi.x = f2tf(v.x); lo.x = f2tf(v.x - __uint_as_float(hi.x));
            hi.y = f2tf(v.y); lo.y = f2tf(v.y - __uint_as_float(hi.y));
            hi.z = f2tf(v.z); lo.z = f2tf(v.z - __uint_as_float(hi.z));
            hi.w = f2tf(v.w); lo.w = f2tf(v.w - __uint_as_float(hi.w));
            *(uint4*)&Bh[kk][bq * 4] = hi;
            *(uint4*)&Bl[kk][bq * 4] = lo;
        }
        __syncthreads();

        #pragma unroll
        for (int ks = 0; ks < 2; ks++) {
            int kb = ks * 8;
            int kfa = kb + (lane & 3);
            unsigned bhf[4][2], blf[4][2];
            #pragma unroll
            for (int nt = 0; nt < 4; nt++) {
                int n = wCol * 32 + nt * 8 + (lane >> 2);
                bhf[nt][0] = Bh[kfa][n];     bhf[nt][1] = Bh[kfa + 4][n];
                blf[nt][0] = Bl[kfa][n];     blf[nt][1] = Bl[kfa + 4][n];
            }
            #pragma unroll
            for (int mt = 0; mt < 4; mt++) {
                int r0 = wRow * 64 + mt * 16 + (lane >> 2);
                unsigned ahf[4], alf[4];
                ahf[0] = Ah[r0][kfa];     ahf[1] = Ah[r0 + 8][kfa];
                ahf[2] = Ah[r0][kfa + 4]; ahf[3] = Ah[r0 + 8][kfa + 4];
                alf[0] = Al[r0][kfa];     alf[1] = Al[r0 + 8][kfa];
                alf[2] = Al[r0][kfa + 4]; alf[3] = Al[r0 + 8][kfa + 4];
                #pragma unroll
                for (int nt = 0; nt < 4; nt++) {
                    mma_tf32(acc[mt][nt], ahf, bhf[nt]);
                    mma_tf32(acc[mt][nt], ahf, blf[nt]);
                    mma_tf32(acc[mt][nt], alf, bhf[nt]);
                }
            }
        }
        __syncthreads();
    }

    // ---- epilogue: bias + relu [+ resid]
    #pragma unroll
    for (int mt = 0; mt < 4; mt++) {
        int r = rowBase + wRow * 64 + mt * 16 + (lane >> 2);
        #pragma unroll
        for (int nt = 0; nt < 4; nt++) {
            int c = colBase + wCol * 32 + nt * 8 + (lane & 3) * 2;
            float b0 = bias[c], b1 = bias[c + 1];
            if (r < M) {
                float v0 = fmaxf(acc[mt][nt][0] + b0, 0.f);
                float v1 = fmaxf(acc[mt][nt][1] + b1, 0.f);
                if (resid) {
                    float2 rv = *(const float2*)&resid[(size_t)r * DN + c];
                    v0 += rv.x; v1 += rv.y;
                }
                *(float2*)&Cmat[(size_t)r * DN + c] = make_float2(v0, v1);
            }
            int r2 = r + 8;
            if (r2 < M) {
                float v2 = fmaxf(acc[mt][nt][2] + b0, 0.f);
                float v3 = fmaxf(acc[mt][nt][3] + b1, 0.f);
                if (resid) {
                    float2 rv = *(const float2*)&resid[(size_t)r2 * DN + c];
                    v2 += rv.x; v3 += rv.y;
                }
                *(float2*)&Cmat[(size_t)r2 * DN + c] = make_float2(v2, v3);
            }
        }
    }
}

// ---------------- batch segment boundaries from sorted batch vector
__global__ void k_starts(const int* __restrict__ batch, int* __restrict__ starts, int N)
{
    int i = blockIdx.x * blockDim.x + threadIdx.x;
    if (i >= N) return;
    int b = batch[i];
    int prev = (i == 0) ? -1 : batch[i - 1];
    for (int v = prev + 1; v <= b; v++) starts[v] = i;
    if (i == N - 1)
        for (int v = b + 1; v <= BNB; v++) starts[v] = N;
}

// ---------------- segment-mean pooling (block per batch, thread per column)
__global__ void k_pool(const float* __restrict__ x, const int* __restrict__ starts,
                       float* __restrict__ pool)
{
    int b = blockIdx.x, c = threadIdx.x;
    int s0 = starts[b], s1 = starts[b + 1];
    float acc = 0.f;
    for (int i = s0; i < s1; i++) acc += x[(size_t)i * DN + c];
    pool[b * DN + c] = acc / fmaxf((float)(s1 - s0), 1.f);
}

// ---------------- edge MLP pooling (warp per edge, lane per output channel)
__global__ void k_epool(const int* __restrict__ src, const float* __restrict__ ea,
                        const int* __restrict__ hbatch,
                        const float* __restrict__ Wem, const float* __restrict__ bem)
{
    __shared__ int hist[BNB];
    for (int t = threadIdx.x; t < BNB; t += blockDim.x) hist[t] = 0;
    __syncthreads();
    int lane = threadIdx.x & 31;
    int wid = (blockIdx.x * blockDim.x + threadIdx.x) >> 5;
    int nw = (gridDim.x * blockDim.x) >> 5;
    float w0 = Wem[lane], w1 = Wem[32 + lane], bb = bem[lane];
    for (int e = wid; e < NEN; e += nw) {
        int b = hbatch[src[e]];
        float2 at = ((const float2*)ea)[e];
        float v = fmaxf(at.x * w0 + at.y * w1 + bb, 0.f);
        atomicAdd(&g_epool[b * 32 + lane], v);
        if (lane == 0) atomicAdd(&hist[b], 1);
    }
    __syncthreads();
    for (int t = threadIdx.x; t < BNB; t += blockDim.x)
        if (hist[t]) atomicAdd(&g_cnt_e[t], hist[t]);
}

__global__ void k_epool_div()
{
    int i = blockIdx.x * blockDim.x + threadIdx.x;
    if (i >= BNB * 32) return;
    g_epool[i] /= fmaxf((float)g_cnt_e[i >> 5], 1.f);
}

// ---------------- final heads: linear + softmax (block per (batch, head))
__global__ void k_head(const float* __restrict__ Wp1, const float* __restrict__ bp1,
                       const float* __restrict__ Wp2, const float* __restrict__ bp2,
                       float* __restrict__ out)
{
    __shared__ float emb[2*DN + 32];
    __shared__ float red[128];
    int b = blockIdx.x, head = blockIdx.y, t = threadIdx.x;
    for (int i = t; i < DN; i += 128) {
        emb[i] = g_hpool[b * DN + i];
        emb[DN + i] = g_opool[b * DN + i];
    }
    if (t < 32) emb[2*DN + t] = g_epool[b * 32 + t];
    __syncthreads();
    const float* Wp = head ? Wp2 : Wp1;
    const float* bp = head ? bp2 : bp1;
    float acc = -INFINITY;
    if (t < CNC) {
        acc = bp[t];
        for (int k = 0; k < 2*DN + 32; k++) acc += emb[k] * Wp[k * CNC + t];
    }
    red[t] = acc;
    __syncthreads();
    for (int s = 64; s > 0; s >>= 1) {
        if (t < s) red[t] = fmaxf(red[t], red[t + s]);
        __syncthreads();
    }
    float mx = red[0];
    __syncthreads();
    float ex = (t < CNC) ? __expf(acc - mx) : 0.f;
    red[t] = ex;
    __syncthreads();
    for (int s = 64; s > 0; s >>= 1) {
        if (t < s) red[t] += red[t + s];
        __syncthreads();
    }
    float sum = red[0];
    if (t < CNC) out[((size_t)b * 2 + head) * CNC + t] = ex / sum;
}

// ---------------- host ----------------
#define SYM(p, s) do { void* tmp__ = 0; cudaGetSymbolAddress(&tmp__, s); p = (decltype(p))tmp__; } while (0)

extern "C" void kernel_launch(void* const* d_in, const int* in_sizes, int n_in,
                              void* d_out, int out_size)
{
    const float* x_human  = (const float*)d_in[0];
    const float* x_object = (const float*)d_in[1];
    const int*   ei_ho    = (const int*)d_in[2];
    const int*   ei_oh    = (const int*)d_in[3];
    const float* ea_ho    = (const float*)d_in[4];
    const float* ea_oh    = (const float*)d_in[5];
    const int*   hbatch   = (const int*)d_in[6];
    const int*   obatch   = (const int*)d_in[7];
    const float* Wsrc_ho  = (const float*)d_in[8];
    const float* Wdst_ho  = (const float*)d_in[9];
    const float* asrc_ho  = (const float*)d_in[10];
    const float* adst_ho  = (const float*)d_in[11];
    const float* Wedge_ho = (const float*)d_in[12];
    const float* aedge_ho = (const float*)d_in[13];
    const float* bias_ho  = (const float*)d_in[14];
    const float* Wsrc_oh  = (const float*)d_in[15];
    const float* Wdst_oh  = (const float*)d_in[16];
    const float* asrc_oh  = (const float*)d_in[17];
    const float* adst_oh  = (const float*)d_in[18];
    const float* Wedge_oh = (const float*)d_in[19];
    const float* aedge_oh = (const float*)d_in[20];
    const float* bias_oh  = (const float*)d_in[21];
    const float* W_emlp   = (const float*)d_in[22];
    const float* b_emlp   = (const float*)d_in[23];
    const float* W_p1     = (const float*)d_in[24];
    const float* b_p1     = (const float*)d_in[25];
    const float* W_p2     = (const float*)d_in[26];
    const float* b_p2     = (const float*)d_in[27];

    float *xh0, *xo0, *agg_h, *agg_o;
    float *ex_ho, *ex_oh;
    float *as_ho, *ad_ho, *as_oh, *ad_oh;
    float *den_ho, *den_oh, *cvec;
    float *hpool, *opool, *epool;
    int *starts_h, *starts_o, *cnt_e;
    SYM(xh0, g_xh);        SYM(xo0, g_xo);
    SYM(agg_h, g_agg_h);   SYM(agg_o, g_agg_o);
    SYM(ex_ho, g_ex_ho);   SYM(ex_oh, g_ex_oh);
    SYM(as_ho, g_as_ho); SYM(ad_ho, g_ad_ho);
    SYM(as_oh, g_as_oh); SYM(ad_oh, g_ad_oh);
    SYM(den_ho, g_den_ho); SYM(den_oh, g_den_oh);
    SYM(cvec, g_cvec);
    SYM(hpool, g_hpool); SYM(opool, g_opool); SYM(epool, g_epool);
    SYM(starts_h, g_starts_h); SYM(starts_o, g_starts_o); SYM(cnt_e, g_cnt_e);
    float* xh1 = xh0 + (size_t)NHN * DN;
    float* xo1 = xo0 + (size_t)NON * DN;

    cudaMemcpyAsync(xh0, x_human,  sizeof(float)*(size_t)NHN*DN, cudaMemcpyDeviceToDevice, 0);
    cudaMemcpyAsync(xo0, x_object, sizeof(float)*(size_t)NON*DN, cudaMemcpyDeviceToDevice, 0);

    int nsBlocksH = (NHN * 32 + 255) / 256;
    int nsBlocksO = (NON * 32 + 255) / 256;
    int eBlocks   = (NEN + 255) / 256;
    int cBlocks   = (NEN * 32) / 256;
    dim3 gg(2, (NON + 127) / 128);

    int cur = 0;
    for (int l = 0; l < LN; l++) {
        float* xh_in  = cur ? xh1 : xh0;
        float* xh_out = cur ? xh0 : xh1;
        float* xo_in  = cur ? xo1 : xo0;
        float* xo_out = cur ? xo0 : xo1;

        k_small<<<1, 256>>>(Wsrc_ho, asrc_ho, Wdst_ho, adst_ho,
                            Wsrc_oh, asrc_oh, Wdst_oh, adst_oh,
                            Wedge_ho, aedge_ho, Wedge_oh, aedge_oh, l);
        cudaMemsetAsync(agg_h, 0, sizeof(float)*(size_t)NHN*DN, 0);
        cudaMemsetAsync(agg_o, 0, sizeof(float)*(size_t)NON*DN, 0);
        cudaMemsetAsync(den_ho,  0, sizeof(float)*NON, 0);
        cudaMemsetAsync(den_oh,  0, sizeof(float)*NHN, 0);

        k_nodescore<<<nsBlocksH, 256>>>(xh_in, 0, 3, as_ho, ad_oh, NHN);
        k_nodescore<<<nsBlocksO, 256>>>(xo_in, 2, 1, as_oh, ad_ho, NON);

        k_edgeAB<<<eBlocks, 256>>>(ei_ho, ei_ho + NEN, ea_ho, as_ho, ad_ho, cvec,     ex_ho, den_ho);
        k_edgeAB<<<eBlocks, 256>>>(ei_oh, ei_oh + NEN, ea_oh, as_oh, ad_oh, cvec + 2, ex_oh, den_oh);
        k_edgeC<<<cBlocks, 256>>>(ei_ho, ei_ho + NEN, ex_ho, den_ho, xh_in, agg_o);
        k_edgeC<<<cBlocks, 256>>>(ei_oh, ei_oh + NEN, ex_oh, den_oh, xo_in, agg_h);

        k_gemm_tc<<<gg, 256>>>(agg_o, Wsrc_ho + (size_t)l*DN*DN, bias_ho + l*DN,
                               l ? xo_in : (const float*)0, xo_out, NON);
        k_gemm_tc<<<gg, 256>>>(agg_h, Wsrc_oh + (size_t)l*DN*DN, bias_oh + l*DN,
                               l ? xh_in : (const float*)0, xh_out, NHN);
        cur ^= 1;
    }
    float* xh_fin = cur ? xh1 : xh0;
    float* xo_fin = cur ? xo1 : xo0;

    k_starts<<<(NHN + 255) / 256, 256>>>(hbatch, starts_h, NHN);
    k_starts<<<(NON + 255) / 256, 256>>>(obatch, starts_o, NON);
    k_pool<<<BNB, 256>>>(xh_fin, starts_h, hpool);
    k_pool<<<BNB, 256>>>(xo_fin, starts_o, opool);

    cudaMemsetAsync(epool, 0, sizeof(float)*BNB*32, 0);
    cudaMemsetAsync(cnt_e, 0, sizeof(int)*BNB, 0);
    k_epool<<<512, 256>>>(ei_ho, ea_ho, hbatch, W_emlp, b_emlp);
    k_epool_div<<<(BNB*32 + 255) / 256, 256>>>();

    k_head<<<dim3(BNB, 2), 128>>>(W_p1, b_p1, W_p2, b_p2, (float*)d_out);
}

// round 6
// speedup vs baseline: 1.3664x; 1.1639x over previous
#include <cuda_runtime.h>
#include <cuda_fp16.h>
#include <math.h>

#define NHN 50000
#define NON 50000
#define NEN 500000
#define DN  256
#define LN  8
#define BNB 512
#define CNC 117

// ---------------- device scratch (static: allocation-free rule) ----------------
__device__ __align__(16) float g_xh[2][NHN*DN];
__device__ __align__(16) float g_xo[2][NON*DN];
__device__ __align__(16) float g_agg_h[NHN*DN];
__device__ __align__(16) float g_agg_o[NON*DN];
__device__ float g_ex_ho[NEN];
__device__ float g_ex_oh[NEN];
__device__ float g_as_ho[NHN];
__device__ float g_ad_ho[NON];
__device__ float g_as_oh[NON];
__device__ float g_ad_oh[NHN];
__device__ float g_den_ho[NON];
__device__ float g_den_oh[NHN];
__device__ __align__(16) float g_wvec[4][DN];   // 0:wsa_ho 1:wda_ho 2:wsa_oh 3:wda_oh
__device__ float g_cvec[4];                      // c_ho[2], c_oh[2]
__device__ __align__(16) float g_hpool[BNB*DN];
__device__ __align__(16) float g_opool[BNB*DN];
__device__ float g_epool[BNB*32];
__device__ int g_starts_h[BNB+1];
__device__ int g_starts_o[BNB+1];
__device__ int g_cnt_e[BNB];

// ---------------- helpers ----------------
__device__ __forceinline__ void red_add4(float* p, float4 v) {
    asm volatile("red.global.add.v4.f32 [%0], {%1,%2,%3,%4};"
                 :: "l"(p), "f"(v.x), "f"(v.y), "f"(v.z), "f"(v.w) : "memory");
}
// split (a,b) -> packed half2 hi + half2 lo (2-term fp16 split, 22-bit effective)
__device__ __forceinline__ void split2(float a, float b, unsigned &hi, unsigned &lo) {
    __half ha = __float2half_rn(a), hb = __float2half_rn(b);
    __half la = __float2half_rn(a - __half2float(ha));
    __half lb = __float2half_rn(b - __half2float(hb));
    hi = (unsigned)__half_as_ushort(ha) | ((unsigned)__half_as_ushort(hb) << 16);
    lo = (unsigned)__half_as_ushort(la) | ((unsigned)__half_as_ushort(lb) << 16);
}
__device__ __forceinline__ void mma_f16(float* d, const unsigned* a, const unsigned* b) {
    asm volatile("mma.sync.aligned.m16n8k16.row.col.f32.f16.f16.f32 "
                 "{%0,%1,%2,%3}, {%4,%5,%6,%7}, {%8,%9}, {%0,%1,%2,%3};"
                 : "+f"(d[0]), "+f"(d[1]), "+f"(d[2]), "+f"(d[3])
                 : "r"(a[0]), "r"(a[1]), "r"(a[2]), "r"(a[3]),
                   "r"(b[0]), "r"(b[1]));
}

// ---------------- per-layer small weights
__global__ void k_small(const float* WsrcHo, const float* asrcHo,
                        const float* WdstHo, const float* adstHo,
                        const float* WsrcOh, const float* asrcOh,
                        const float* WdstOh, const float* adstOh,
                        const float* WedgeHo, const float* aedgeHo,
                        const float* WedgeOh, const float* aedgeOh, int l)
{
    int k = threadIdx.x;
    const float* W0 = WsrcHo + (size_t)l*DN*DN + (size_t)k*DN;
    const float* W1 = WdstHo + (size_t)l*DN*DN + (size_t)k*DN;
    const float* W2 = WsrcOh + (size_t)l*DN*DN + (size_t)k*DN;
    const float* W3 = WdstOh + (size_t)l*DN*DN + (size_t)k*DN;
    const float* a0 = asrcHo + l*DN;
    const float* a1 = adstHo + l*DN;
    const float* a2 = asrcOh + l*DN;
    const float* a3 = adstOh + l*DN;
    float s0 = 0.f, s1 = 0.f, s2 = 0.f, s3 = 0.f;
    for (int n = 0; n < DN; n++) {
        s0 += W0[n] * a0[n];
        s1 += W1[n] * a1[n];
        s2 += W2[n] * a2[n];
        s3 += W3[n] * a3[n];
    }
    g_wvec[0][k] = s0; g_wvec[1][k] = s1; g_wvec[2][k] = s2; g_wvec[3][k] = s3;
    if (k < 2) {
        float c = 0.f;
        const float* We = WedgeHo + (size_t)l*2*DN + (size_t)k*DN;
        const float* ae = aedgeHo + l*DN;
        for (int n = 0; n < DN; n++) c += We[n] * ae[n];
        g_cvec[k] = c;
    } else if (k < 4) {
        int r = k - 2;
        float c = 0.f;
        const float* We = WedgeOh + (size_t)l*2*DN + (size_t)r*DN;
        const float* ae = aedgeOh + l*DN;
        for (int n = 0; n < DN; n++) c += We[n] * ae[n];
        g_cvec[k] = c;
    }
}

// ---------------- node scores: two dot products per node (warp per node)
__global__ void k_nodescore(const float* __restrict__ x, int ia, int ib,
                            float* __restrict__ outA, float* __restrict__ outB, int N)
{
    int w = (blockIdx.x * blockDim.x + threadIdx.x) >> 5;
    int lane = threadIdx.x & 31;
    if (w >= N) return;
    const float4* xr = (const float4*)(x + (size_t)w * DN);
    const float4* va = (const float4*)g_wvec[ia];
    const float4* vb = (const float4*)g_wvec[ib];
    float4 x0 = xr[lane], x1 = xr[lane + 32];
    float4 a0 = va[lane], a1 = va[lane + 32];
    float4 b0 = vb[lane], b1 = vb[lane + 32];
    float dA = x0.x*a0.x + x0.y*a0.y + x0.z*a0.z + x0.w*a0.w
             + x1.x*a1.x + x1.y*a1.y + x1.z*a1.z + x1.w*a1.w;
    float dB = x0.x*b0.x + x0.y*b0.y + x0.z*b0.z + x0.w*b0.w
             + x1.x*b1.x + x1.y*b1.y + x1.z*b1.z + x1.w*b1.w;
    #pragma unroll
    for (int off = 16; off > 0; off >>= 1) {
        dA += __shfl_down_sync(0xffffffffu, dA, off);
        dB += __shfl_down_sync(0xffffffffu, dB, off);
    }
    if (lane == 0) { outA[w] = dA; outB[w] = dB; }
}

// ---------------- fused edge pass: logit -> exp + segment sum
__global__ void k_edgeAB(const int* __restrict__ src, const int* __restrict__ dst,
                         const float* __restrict__ ea,
                         const float* __restrict__ a_s, const float* __restrict__ a_d,
                         const float* __restrict__ cpair,
                         float* __restrict__ ex, float* __restrict__ den)
{
    int e = blockIdx.x * blockDim.x + threadIdx.x;
    if (e >= NEN) return;
    int s = src[e], d = dst[e];
    float2 at = ((const float2*)ea)[e];
    float lg = a_s[s] + a_d[d] + at.x * cpair[0] + at.y * cpair[1];
    lg = (lg > 0.f) ? lg : 0.2f * lg;
    float v = __expf(lg);
    ex[e] = v;
    atomicAdd(&den[d], v);
}

// ---------------- edge pass C: weighted gather + scatter-add (warp per edge)
__global__ void k_edgeC(const int* __restrict__ src, const int* __restrict__ dst,
                        const float* __restrict__ ex, const float* __restrict__ den,
                        const float* __restrict__ x, float* __restrict__ agg)
{
    int e = (blockIdx.x * blockDim.x + threadIdx.x) >> 5;
    if (e >= NEN) return;
    int lane = threadIdx.x & 31;
    int s = src[e], d = dst[e];
    float w = ex[e] / den[d];
    const float4* xs = (const float4*)(x + (size_t)s * DN);
    float4 v0 = xs[lane], v1 = xs[lane + 32];
    v0.x *= w; v0.y *= w; v0.z *= w; v0.w *= w;
    v1.x *= w; v1.y *= w; v1.z *= w; v1.w *= w;
    float* base = agg + (size_t)d * DN;
    red_add4(base + lane * 4, v0);
    red_add4(base + 128 + lane * 4, v1);
}

// ---------------- tensor-core GEMM (2-term fp16 split, 3 products = 22-bit mantissa):
// out = relu(A@W + bias) [+ resid]; 128x128 tile, BK=16, 8 warps (2x4), warp tile 64x32
#define GBK 16
#define ASTR 12     // A smem row stride in words (12r+c conflict-free mod 32)
#define BSTR 136    // B smem row stride in words (136 = 8 mod 32, conflict-free)
__global__ void __launch_bounds__(256, 2)
k_gemm_tc(const float* __restrict__ A, const float* __restrict__ W,
          const float* __restrict__ bias, const float* __restrict__ resid,
          float* __restrict__ Cmat, int M)
{
    // packed half2 along K: word (r, k2) = half2(A[r][2k2], A[r][2k2+1])
    __shared__ unsigned Ah[128 * ASTR];
    __shared__ unsigned Al[128 * ASTR];
    __shared__ unsigned Bh[8 * BSTR];   // word (k2, n) = half2(W[2k2][n], W[2k2+1][n])
    __shared__ unsigned Bl[8 * BSTR];

    int tid  = threadIdx.x;
    int lane = tid & 31;
    int warp = tid >> 5;
    int wRow = warp >> 2;          // 0..1
    int wCol = warp & 3;           // 0..3
    int rowBase = blockIdx.y * 128;
    int colBase = blockIdx.x * 128;

    float acc[4][4][4];
    #pragma unroll
    for (int i = 0; i < 4; i++)
        #pragma unroll
        for (int j = 0; j < 4; j++)
            #pragma unroll
            for (int k = 0; k < 4; k++) acc[i][j][k] = 0.f;

    int ar = tid >> 1, aq = tid & 1;   // A stage: row ar, k-half aq (8 floats)
    int kp = tid >> 5, nc = tid & 31;  // B stage: k-pair kp, 4 cols at nc*4

    for (int k0 = 0; k0 < DN; k0 += GBK) {
        // ---- stage A (128 x 16) -> hi/lo half2
        {
            int gr = rowBase + ar;
            float4 v0 = make_float4(0.f,0.f,0.f,0.f), v1 = v0;
            if (gr < M) {
                v0 = *(const float4*)&A[(size_t)gr * DN + k0 + aq * 8];
                v1 = *(const float4*)&A[(size_t)gr * DN + k0 + aq * 8 + 4];
            }
            uint4 hi, lo;
            split2(v0.x, v0.y, hi.x, lo.x);
            split2(v0.z, v0.w, hi.y, lo.y);
            split2(v1.x, v1.y, hi.z, lo.z);
            split2(v1.z, v1.w, hi.w, lo.w);
            *(uint4*)&Ah[ar * ASTR + aq * 4] = hi;
            *(uint4*)&Al[ar * ASTR + aq * 4] = lo;
        }
        // ---- stage B (16 x 128) -> hi/lo half2 (pack along k)
        {
            float4 u0 = *(const float4*)&W[(size_t)(k0 + 2*kp)     * DN + colBase + nc * 4];
            float4 u1 = *(const float4*)&W[(size_t)(k0 + 2*kp + 1) * DN + colBase + nc * 4];
            uint4 hi, lo;
            split2(u0.x, u1.x, hi.x, lo.x);
            split2(u0.y, u1.y, hi.y, lo.y);
            split2(u0.z, u1.z, hi.z, lo.z);
            split2(u0.w, u1.w, hi.w, lo.w);
            *(uint4*)&Bh[kp * BSTR + nc * 4] = hi;
            *(uint4*)&Bl[kp * BSTR + nc * 4] = lo;
        }
        __syncthreads();

        int k2 = lane & 3;
        unsigned bhf[4][2], blf[4][2];
        #pragma unroll
        for (int nt = 0; nt < 4; nt++) {
            int n = wCol * 32 + nt * 8 + (lane >> 2);
            bhf[nt][0] = Bh[k2 * BSTR + n];       bhf[nt][1] = Bh[(k2 + 4) * BSTR + n];
            blf[nt][0] = Bl[k2 * BSTR + n];       blf[nt][1] = Bl[(k2 + 4) * BSTR + n];
        }
        #pragma unroll
        for (int mt = 0; mt < 4; mt++) {
            int r = wRow * 64 + mt * 16 + (lane >> 2);
            unsigned ahf[4], alf[4];
            ahf[0] = Ah[r * ASTR + k2];           ahf[1] = Ah[(r + 8) * ASTR + k2];
            ahf[2] = Ah[r * ASTR + k2 + 4];       ahf[3] = Ah[(r + 8) * ASTR + k2 + 4];
            alf[0] = Al[r * ASTR + k2];           alf[1] = Al[(r + 8) * ASTR + k2];
            alf[2] = Al[r * ASTR + k2 + 4];       alf[3] = Al[(r + 8) * ASTR + k2 + 4];
            #pragma unroll
            for (int nt = 0; nt < 4; nt++) {
                mma_f16(acc[mt][nt], ahf, bhf[nt]);
                mma_f16(acc[mt][nt], ahf, blf[nt]);
                mma_f16(acc[mt][nt], alf, bhf[nt]);
            }
        }
        __syncthreads();
    }

    // ---- epilogue: bias + relu [+ resid]  (m16n8 layout: rows lane>>2, +8; cols 2*(lane&3)+{0,1})
    #pragma unroll
    for (int mt = 0; mt < 4; mt++) {
        int r = rowBase + wRow * 64 + mt * 16 + (lane >> 2);
        #pragma unroll
        for (int nt = 0; nt < 4; nt++) {
            int c = colBase + wCol * 32 + nt * 8 + (lane & 3) * 2;
            float b0 = bias[c], b1 = bias[c + 1];
            if (r < M) {
                float v0 = fmaxf(acc[mt][nt][0] + b0, 0.f);
                float v1 = fmaxf(acc[mt][nt][1] + b1, 0.f);
                if (resid) {
                    float2 rv = *(const float2*)&resid[(size_t)r * DN + c];
                    v0 += rv.x; v1 += rv.y;
                }
                *(float2*)&Cmat[(size_t)r * DN + c] = make_float2(v0, v1);
            }
            int r2 = r + 8;
            if (r2 < M) {
                float v2 = fmaxf(acc[mt][nt][2] + b0, 0.f);
                float v3 = fmaxf(acc[mt][nt][3] + b1, 0.f);
                if (resid) {
                    float2 rv = *(const float2*)&resid[(size_t)r2 * DN + c];
                    v2 += rv.x; v3 += rv.y;
                }
                *(float2*)&Cmat[(size_t)r2 * DN + c] = make_float2(v2, v3);
            }
        }
    }
}

// ---------------- batch segment boundaries from sorted batch vector
__global__ void k_starts(const int* __restrict__ batch, int* __restrict__ starts, int N)
{
    int i = blockIdx.x * blockDim.x + threadIdx.x;
    if (i >= N) return;
    int b = batch[i];
    int prev = (i == 0) ? -1 : batch[i - 1];
    for (int v = prev + 1; v <= b; v++) starts[v] = i;
    if (i == N - 1)
        for (int v = b + 1; v <= BNB; v++) starts[v] = N;
}

// ---------------- segment-mean pooling (block per batch, thread per column)
__global__ void k_pool(const float* __restrict__ x, const int* __restrict__ starts,
                       float* __restrict__ pool)
{
    int b = blockIdx.x, c = threadIdx.x;
    int s0 = starts[b], s1 = starts[b + 1];
    float acc = 0.f;
    for (int i = s0; i < s1; i++) acc += x[(size_t)i * DN + c];
    pool[b * DN + c] = acc / fmaxf((float)(s1 - s0), 1.f);
}

// ---------------- edge MLP pooling (warp per edge, lane per output channel)
__global__ void k_epool(const int* __restrict__ src, const float* __restrict__ ea,
                        const int* __restrict__ hbatch,
                        const float* __restrict__ Wem, const float* __restrict__ bem)
{
    __shared__ int hist[BNB];
    for (int t = threadIdx.x; t < BNB; t += blockDim.x) hist[t] = 0;
    __syncthreads();
    int lane = threadIdx.x & 31;
    int wid = (blockIdx.x * blockDim.x + threadIdx.x) >> 5;
    int nw = (gridDim.x * blockDim.x) >> 5;
    float w0 = Wem[lane], w1 = Wem[32 + lane], bb = bem[lane];
    for (int e = wid; e < NEN; e += nw) {
        int b = hbatch[src[e]];
        float2 at = ((const float2*)ea)[e];
        float v = fmaxf(at.x * w0 + at.y * w1 + bb, 0.f);
        atomicAdd(&g_epool[b * 32 + lane], v);
        if (lane == 0) atomicAdd(&hist[b], 1);
    }
    __syncthreads();
    for (int t = threadIdx.x; t < BNB; t += blockDim.x)
        if (hist[t]) atomicAdd(&g_cnt_e[t], hist[t]);
}

__global__ void k_epool_div()
{
    int i = blockIdx.x * blockDim.x + threadIdx.x;
    if (i >= BNB * 32) return;
    g_epool[i] /= fmaxf((float)g_cnt_e[i >> 5], 1.f);
}

// ---------------- final heads: linear + softmax (block per (batch, head))
__global__ void k_head(const float* __restrict__ Wp1, const float* __restrict__ bp1,
                       const float* __restrict__ Wp2, const float* __restrict__ bp2,
                       float* __restrict__ out)
{
    __shared__ float emb[2*DN + 32];
    __shared__ float red[128];
    int b = blockIdx.x, head = blockIdx.y, t = threadIdx.x;
    for (int i = t; i < DN; i += 128) {
        emb[i] = g_hpool[b * DN + i];
        emb[DN + i] = g_opool[b * DN + i];
    }
    if (t < 32) emb[2*DN + t] = g_epool[b * 32 + t];
    __syncthreads();
    const float* Wp = head ? Wp2 : Wp1;
    const float* bp = head ? bp2 : bp1;
    float acc = -INFINITY;
    if (t < CNC) {
        acc = bp[t];
        for (int k = 0; k < 2*DN + 32; k++) acc += emb[k] * Wp[k * CNC + t];
    }
    red[t] = acc;
    __syncthreads();
    for (int s = 64; s > 0; s >>= 1) {
        if (t < s) red[t] = fmaxf(red[t], red[t + s]);
        __syncthreads();
    }
    float mx = red[0];
    __syncthreads();
    float ex = (t < CNC) ? __expf(acc - mx) : 0.f;
    red[t] = ex;
    __syncthreads();
    for (int s = 64; s > 0; s >>= 1) {
        if (t < s) red[t] += red[t + s];
        __syncthreads();
    }
    float sum = red[0];
    if (t < CNC) out[((size_t)b * 2 + head) * CNC + t] = ex / sum;
}

// ---------------- host ----------------
#define SYM(p, s) do { void* tmp__ = 0; cudaGetSymbolAddress(&tmp__, s); p = (decltype(p))tmp__; } while (0)

extern "C" void kernel_launch(void* const* d_in, const int* in_sizes, int n_in,
                              void* d_out, int out_size)
{
    const float* x_human  = (const float*)d_in[0];
    const float* x_object = (const float*)d_in[1];
    const int*   ei_ho    = (const int*)d_in[2];
    const int*   ei_oh    = (const int*)d_in[3];
    const float* ea_ho    = (const float*)d_in[4];
    const float* ea_oh    = (const float*)d_in[5];
    const int*   hbatch   = (const int*)d_in[6];
    const int*   obatch   = (const int*)d_in[7];
    const float* Wsrc_ho  = (const float*)d_in[8];
    const float* Wdst_ho  = (const float*)d_in[9];
    const float* asrc_ho  = (const float*)d_in[10];
    const float* adst_ho  = (const float*)d_in[11];
    const float* Wedge_ho = (const float*)d_in[12];
    const float* aedge_ho = (const float*)d_in[13];
    const float* bias_ho  = (const float*)d_in[14];
    const float* Wsrc_oh  = (const float*)d_in[15];
    const float* Wdst_oh  = (const float*)d_in[16];
    const float* asrc_oh  = (const float*)d_in[17];
    const float* adst_oh  = (const float*)d_in[18];
    const float* Wedge_oh = (const float*)d_in[19];
    const float* aedge_oh = (const float*)d_in[20];
    const float* bias_oh  = (const float*)d_in[21];
    const float* W_emlp   = (const float*)d_in[22];
    const float* b_emlp   = (const float*)d_in[23];
    const float* W_p1     = (const float*)d_in[24];
    const float* b_p1     = (const float*)d_in[25];
    const float* W_p2     = (const float*)d_in[26];
    const float* b_p2     = (const float*)d_in[27];

    float *xh0, *xo0, *agg_h, *agg_o;
    float *ex_ho, *ex_oh;
    float *as_ho, *ad_ho, *as_oh, *ad_oh;
    float *den_ho, *den_oh, *cvec;
    float *hpool, *opool, *epool;
    int *starts_h, *starts_o, *cnt_e;
    SYM(xh0, g_xh);        SYM(xo0, g_xo);
    SYM(agg_h, g_agg_h);   SYM(agg_o, g_agg_o);
    SYM(ex_ho, g_ex_ho);   SYM(ex_oh, g_ex_oh);
    SYM(as_ho, g_as_ho); SYM(ad_ho, g_ad_ho);
    SYM(as_oh, g_as_oh); SYM(ad_oh, g_ad_oh);
    SYM(den_ho, g_den_ho); SYM(den_oh, g_den_oh);
    SYM(cvec, g_cvec);
    SYM(hpool, g_hpool); SYM(opool, g_opool); SYM(epool, g_epool);
    SYM(starts_h, g_starts_h); SYM(starts_o, g_starts_o); SYM(cnt_e, g_cnt_e);
    float* xh1 = xh0 + (size_t)NHN * DN;
    float* xo1 = xo0 + (size_t)NON * DN;

    cudaMemcpyAsync(xh0, x_human,  sizeof(float)*(size_t)NHN*DN, cudaMemcpyDeviceToDevice, 0);
    cudaMemcpyAsync(xo0, x_object, sizeof(float)*(size_t)NON*DN, cudaMemcpyDeviceToDevice, 0);

    int nsBlocksH = (NHN * 32 + 255) / 256;
    int nsBlocksO = (NON * 32 + 255) / 256;
    int eBlocks   = (NEN + 255) / 256;
    int cBlocks   = (NEN * 32) / 256;
    dim3 gg(2, (NON + 127) / 128);

    int cur = 0;
    for (int l = 0; l < LN; l++) {
        float* xh_in  = cur ? xh1 : xh0;
        float* xh_out = cur ? xh0 : xh1;
        float* xo_in  = cur ? xo1 : xo0;
        float* xo_out = cur ? xo0 : xo1;

        k_small<<<1, 256>>>(Wsrc_ho, asrc_ho, Wdst_ho, adst_ho,
                            Wsrc_oh, asrc_oh, Wdst_oh, adst_oh,
                            Wedge_ho, aedge_ho, Wedge_oh, aedge_oh, l);
        cudaMemsetAsync(agg_h, 0, sizeof(float)*(size_t)NHN*DN, 0);
        cudaMemsetAsync(agg_o, 0, sizeof(float)*(size_t)NON*DN, 0);
        cudaMemsetAsync(den_ho,  0, sizeof(float)*NON, 0);
        cudaMemsetAsync(den_oh,  0, sizeof(float)*NHN, 0);

        k_nodescore<<<nsBlocksH, 256>>>(xh_in, 0, 3, as_ho, ad_oh, NHN);
        k_nodescore<<<nsBlocksO, 256>>>(xo_in, 2, 1, as_oh, ad_ho, NON);

        k_edgeAB<<<eBlocks, 256>>>(ei_ho, ei_ho + NEN, ea_ho, as_ho, ad_ho, cvec,     ex_ho, den_ho);
        k_edgeAB<<<eBlocks, 256>>>(ei_oh, ei_oh + NEN, ea_oh, as_oh, ad_oh, cvec + 2, ex_oh, den_oh);
        k_edgeC<<<cBlocks, 256>>>(ei_ho, ei_ho + NEN, ex_ho, den_ho, xh_in, agg_o);
        k_edgeC<<<cBlocks, 256>>>(ei_oh, ei_oh + NEN, ex_oh, den_oh, xo_in, agg_h);

        k_gemm_tc<<<gg, 256>>>(agg_o, Wsrc_ho + (size_t)l*DN*DN, bias_ho + l*DN,
                               l ? xo_in : (const float*)0, xo_out, NON);
        k_gemm_tc<<<gg, 256>>>(agg_h, Wsrc_oh + (size_t)l*DN*DN, bias_oh + l*DN,
                               l ? xh_in : (const float*)0, xh_out, NHN);
        cur ^= 1;
    }
    float* xh_fin = cur ? xh1 : xh0;
    float* xo_fin = cur ? xo1 : xo0;

    k_starts<<<(NHN + 255) / 256, 256>>>(hbatch, starts_h, NHN);
    k_starts<<<(NON + 255) / 256, 256>>>(obatch, starts_o, NON);
    k_pool<<<BNB, 256>>>(xh_fin, starts_h, hpool);
    k_pool<<<BNB, 256>>>(xo_fin, starts_o, opool);

    cudaMemsetAsync(epool, 0, sizeof(float)*BNB*32, 0);
    cudaMemsetAsync(cnt_e, 0, sizeof(int)*BNB, 0);
    k_epool<<<512, 256>>>(ei_ho, ea_ho, hbatch, W_emlp, b_emlp);
    k_epool_div<<<(BNB*32 + 255) / 256, 256>>>();

    k_head<<<dim3(BNB, 2), 128>>>(W_p1, b_p1, W_p2, b_p2, (float*)d_out);
}